// round 15
// baseline (speedup 1.0000x reference)
#include <cuda_runtime.h>

#define SEQ       128
#define BATCH     512
#define INPUT_DIM 128
#define HIDDEN    128
#define NQ        8

typedef unsigned long long u64;

__device__ __forceinline__ u64 pk(float lo, float hi) {
    u64 r; asm("mov.b64 %0, {%1, %2};" : "=l"(r) : "f"(lo), "f"(hi)); return r;
}
__device__ __forceinline__ void upk(u64 v, float& lo, float& hi) {
    asm("mov.b64 {%0, %1}, %2;" : "=f"(lo), "=f"(hi) : "l"(v));
}
#define FMA2(o,a,b,c) asm("fma.rn.f32x2 %0, %1, %2, %3;" : "=l"(o) : "l"(a), "l"(b), "l"(c))

// ------ recurrent kernel: 4 INDEPENDENT warps/block (warp w <-> batch 4*bid+w) ------
// x-part fused (no pre-kernel); h lives in registers (lane owns h[4l..4l+3]).
__global__ __launch_bounds__(128)
void qlstm_all(const float* __restrict__ inputs,  // [SEQ,BATCH,INPUT_DIM]
               const float* __restrict__ Wq,
               const float* __restrict__ bq,
               const float* __restrict__ pf,
               const float* __restrict__ pi_,
               const float* __restrict__ pg,
               const float* __restrict__ po,
               const float* __restrict__ Wf, const float* __restrict__ bf,
               const float* __restrict__ Wi, const float* __restrict__ bi,
               const float* __restrict__ Wg, const float* __restrict__ bg,
               const float* __restrict__ Wo, const float* __restrict__ bo,
               float* __restrict__ out)
{
    const int tid  = threadIdx.x;
    const int wid  = tid >> 5;
    const int lane = tid & 31;
    const int b    = blockIdx.x * 4 + wid;   // this warp's batch element
    const int g    = lane >> 3;              // gate 0..3 (f,i,g,o)
    const int v    = lane & 7;               // output wire for the DP
    const unsigned FM = 0xffffffffu;

    __shared__ float4 sWqX[8][32];               // 4KB: Wq rows 0..7, x-part cols 4l..4l+3
    __shared__ float4 sWqH[8][32];               // 4KB: Wq rows 0..7, h-part cols 4l..4l+3
    __shared__ float4 sWg[NQ][4][32];            // 16KB: (Wf,Wi,Wg,Wo) at h=4*lane+u, wire w
    __shared__ __align__(16) float zsm[4][NQ][4];// per-warp [wire][gate]

    // ---- per-lane circuit constants (lane's gate), FULL angles ----
    float Cg[NQ], Sg[NQ], cg[NQ], sg[NQ];
    {
        const float* prm = (g == 0) ? pf : (g == 1) ? pi_ : (g == 2) ? pg : po;
        #pragma unroll
        for (int w = 0; w < NQ; w++) {
            __sincosf(prm[w],      &Sg[w], &Cg[w]);   // d0 layer
            __sincosf(prm[NQ + w], &sg[w], &cg[w]);   // d1 layer
        }
    }
    // ---- weights to smem (cooperative, once) ----
    {
        const float4* Wq4 = (const float4*)Wq;
        for (int i = tid; i < 256; i += 128) {
            sWqX[i >> 5][i & 31] = Wq4[(i >> 5) * 64 + (i & 31)];
            sWqH[i >> 5][i & 31] = Wq4[(i >> 5) * 64 + 32 + (i & 31)];
        }
        for (int i = tid; i < HIDDEN * NQ; i += 128) {
            int h = i >> 3, w = i & 7;
            sWg[w][h & 3][h >> 2] = make_float4(Wf[i], Wi[i], Wg[i], Wo[i]);
        }
    }

    // per-lane LSTM constants for units 4*lane..4*lane+3 (float4 loads)
    const float4 bf4 = ((const float4*)bf)[lane];
    const float4 bi4 = ((const float4*)bi)[lane];
    const float4 bg4 = ((const float4*)bg)[lane];
    const float4 bo4 = ((const float4*)bo)[lane];
    const float  bqr = bq[v];

    float4 hv = make_float4(0.f, 0.f, 0.f, 0.f);   // h[4l..4l+3], registers only
    float  cv[4] = {0.f, 0.f, 0.f, 0.f};

    const float* inb = inputs + (size_t)b * INPUT_DIM;
    float4 xcur = ((const float4*)inb)[lane];      // x_t for t=0
    __syncthreads();   // weights visible (ONLY block barrier)

    for (int t = 0; t < SEQ; t++) {
        // ---- q_in GEMM: x-part + h-part partials, 9-shfl multi-reduce ----
        float acc[8];
        #pragma unroll
        for (int r = 0; r < 8; r++) {
            float4 wx = sWqX[r][lane];
            float4 wh = sWqH[r][lane];
            float a = xcur.x * wx.x;
            a = fmaf(xcur.y, wx.y, a); a = fmaf(xcur.z, wx.z, a); a = fmaf(xcur.w, wx.w, a);
            a = fmaf(hv.x, wh.x, a);   a = fmaf(hv.y, wh.y, a);
            a = fmaf(hv.z, wh.z, a);   a = fmaf(hv.w, wh.w, a);
            acc[r] = a;
        }
        float y;
        {
            int t0 = lane & 1;
            float s0 = t0 ? acc[0] : acc[1], s1 = t0 ? acc[2] : acc[3];
            float s2 = t0 ? acc[4] : acc[5], s3 = t0 ? acc[6] : acc[7];
            float r0 = __shfl_xor_sync(FM, s0, 1);
            float r1 = __shfl_xor_sync(FM, s1, 1);
            float r2 = __shfl_xor_sync(FM, s2, 1);
            float r3 = __shfl_xor_sync(FM, s3, 1);
            float w0_ = (t0 ? acc[1] : acc[0]) + r0;
            float w1_ = (t0 ? acc[3] : acc[2]) + r1;
            float w2_ = (t0 ? acc[5] : acc[4]) + r2;
            float w3_ = (t0 ? acc[7] : acc[6]) + r3;
            int t1 = (lane >> 1) & 1;
            float s4 = t1 ? w0_ : w1_, s5 = t1 ? w2_ : w3_;
            float r4 = __shfl_xor_sync(FM, s4, 2);
            float r5 = __shfl_xor_sync(FM, s5, 2);
            float x0_ = (t1 ? w1_ : w0_) + r4;
            float x1_ = (t1 ? w3_ : w2_) + r5;
            int t2 = (lane >> 2) & 1;
            float s6 = t2 ? x0_ : x1_;
            float r6 = __shfl_xor_sync(FM, s6, 4);
            y = (t2 ? x1_ : x0_) + r6;
            y += __shfl_xor_sync(FM, y, 8);
            y += __shfl_xor_sync(FM, y, 16);   // row (lane&7) total, ALL lanes
        }
        // prefetch next x (off critical path)
        float4 xnext = make_float4(0.f, 0.f, 0.f, 0.f);
        if (t + 1 < SEQ)
            xnext = ((const float4*)(inputs + ((size_t)(t + 1) * BATCH + b) * INPUT_DIM))[lane];

        // sincos of this lane's row (wire v); cs of wire j lives in lanes with v=j
        float sq, cq;
        __sincosf(y + bqr, &sq, &cq);

        // ---- Heisenberg DP (real 4-state), lane computes z[g][v] ----
        float a_ = 1.f, bb = 0.f, c_ = 0.f, d_ = 0.f;
        #pragma unroll
        for (int j = 7; j >= 0; j--) {
            float zf, xf, yf;
            if (j == 7) { zf = 0.f; xf = 1.f; yf = 0.f; }
            else {
                float cqj = __shfl_sync(FM, cq, j + 1);
                float sqj = __shfl_sync(FM, sq, j + 1);
                zf = Cg[j + 1] * cqj;
                xf = Sg[j + 1] * cqj;
                yf = -sqj;
            }
            if (j <= v) {
                float cj = cg[j], sj = sg[j];
                float na = cj * fmaf(yf, d_, bb * zf);
                float nb = cj * fmaf(xf, c_, a_);
                float nc = -sj * fmaf(xf, a_, c_);
                float nd = -sj * fmaf(-yf, bb, d_ * zf);
                a_ = na; bb = nb; c_ = nc; d_ = nd;
            }
        }
        {
            float cq0 = __shfl_sync(FM, cq, 0);
            float sq0 = __shfl_sync(FM, sq, 0);
            float E = a_;
            E = fmaf(Sg[0] * cq0, c_, E);
            E = fmaf(Cg[0] * cq0, bb, E);
            E = fmaf(-sq0, d_, E);
            zsm[wid][v][g] = E;
        }
        __syncwarp();

        // ---- epilogue: units 4*lane+u; z broadcast from smem ----
        float4 zw[8];
        #pragma unroll
        for (int w = 0; w < NQ; w++) zw[w] = *(const float4*)&zsm[wid][w][0];

        float hn[4];
        #pragma unroll
        for (int u = 0; u < 4; u++) {
            float bfv = (u == 0) ? bf4.x : (u == 1) ? bf4.y : (u == 2) ? bf4.z : bf4.w;
            float biv = (u == 0) ? bi4.x : (u == 1) ? bi4.y : (u == 2) ? bi4.z : bi4.w;
            float bgv = (u == 0) ? bg4.x : (u == 1) ? bg4.y : (u == 2) ? bg4.z : bg4.w;
            float bov = (u == 0) ? bo4.x : (u == 1) ? bo4.y : (u == 2) ? bo4.z : bo4.w;
            u64 accfi = pk(bfv, biv);
            u64 accgo = pk(bgv, bov);
            #pragma unroll
            for (int w = 0; w < NQ; w++) {
                float4 ww = sWg[w][u][lane];
                FMA2(accfi, pk(zw[w].x, zw[w].y), pk(ww.x, ww.y), accfi);
                FMA2(accgo, pk(zw[w].z, zw[w].w), pk(ww.z, ww.w), accgo);
            }
            float accf, acci, accg, acco;
            upk(accfi, accf, acci);
            upk(accgo, accg, acco);

            // batched reciprocals: one rcp serves sigmoid(f), sigmoid(i), tanh(g), sigmoid(o)
            float ef = __expf(-accf), ei = __expf(-acci);
            float e2 = __expf(2.f * accg), eo = __expf(-acco);
            float df = 1.f + ef, di = 1.f + ei, dg = e2 + 1.f, do_ = 1.f + eo;
            float P2 = df * di, P3 = P2 * dg, P4 = P3 * do_;
            float r  = __fdividef(1.f, P4);
            float og = r * P3;            // 1/do_
            float r3 = r * do_;           // 1/P3
            float rg = r3 * P2;           // 1/dg
            float r2 = r3 * dg;           // 1/P2
            float ig = r2 * df;           // 1/di
            float fg = r2 * di;           // 1/df
            float gg = (e2 - 1.f) * rg;   // tanh(accg)

            cv[u] = fmaf(fg, cv[u], ig * gg);
            float e2c = __expf(2.f * cv[u]);
            hn[u] = og * __fdividef(e2c - 1.f, e2c + 1.f);
        }
        hv = make_float4(hn[0], hn[1], hn[2], hn[3]);   // h stays in registers

        ((float4*)(out + (size_t)t * BATCH * HIDDEN + (size_t)b * HIDDEN))[lane] = hv;
        xcur = xnext;
        __syncwarp();   // zsm reuse next iteration
    }

    // ---- final hx, cx ----
    size_t base = (size_t)SEQ * BATCH * HIDDEN;
    ((float4*)(out + base + (size_t)b * HIDDEN))[lane] = hv;
    ((float4*)(out + base + (size_t)BATCH * HIDDEN + (size_t)b * HIDDEN))[lane]
        = make_float4(cv[0], cv[1], cv[2], cv[3]);
}

extern "C" void kernel_launch(void* const* d_in, const int* in_sizes, int n_in,
                              void* d_out, int out_size)
{
    const float* inputs = (const float*)d_in[0];
    const float* Wq     = (const float*)d_in[1];
    const float* bq     = (const float*)d_in[2];
    const float* pf     = (const float*)d_in[3];
    const float* pi_    = (const float*)d_in[4];
    const float* pg     = (const float*)d_in[5];
    const float* po     = (const float*)d_in[6];
    const float* Wf     = (const float*)d_in[7];
    const float* bf     = (const float*)d_in[8];
    const float* Wi     = (const float*)d_in[9];
    const float* bi     = (const float*)d_in[10];
    const float* Wg     = (const float*)d_in[11];
    const float* bg     = (const float*)d_in[12];
    const float* Wo     = (const float*)d_in[13];
    const float* bo     = (const float*)d_in[14];
    float* out = (float*)d_out;

    qlstm_all<<<BATCH / 4, 128>>>(inputs, Wq, bq, pf, pi_, pg, po,
                                  Wf, bf, Wi, bi, Wg, bg, Wo, bo, out);
}

// round 16
// speedup vs baseline: 1.1220x; 1.1220x over previous
#include <cuda_runtime.h>

#define SEQ       128
#define BATCH     512
#define INPUT_DIM 128
#define HIDDEN    128
#define NQ        8

typedef unsigned long long u64;

__device__ __forceinline__ u64 pk(float lo, float hi) {
    u64 r; asm("mov.b64 %0, {%1, %2};" : "=l"(r) : "f"(lo), "f"(hi)); return r;
}
__device__ __forceinline__ void upk(u64 v, float& lo, float& hi) {
    asm("mov.b64 {%0, %1}, %2;" : "=f"(lo), "=f"(hi) : "l"(v));
}
#define FMA2(o,a,b,c) asm("fma.rn.f32x2 %0, %1, %2, %3;" : "=l"(o) : "l"(a), "l"(b), "l"(c))
#define ADD2(o,a,b)   asm("add.rn.f32x2 %0, %1, %2;"     : "=l"(o) : "l"(a), "l"(b))

// Precomputed x-part of q_in (+ bias): [SEQ*BATCH, 8]  (2MB device scratch)
__device__ float g_qx[SEQ * BATCH * NQ];

// ---------------- pre-kernel: g_qx[tb][r] = Wq[r, :128] . x[tb] + bq[r] ----------------
__global__ __launch_bounds__(128, 8)
void qx_pre(const float* __restrict__ inputs, const float* __restrict__ Wq,
            const float* __restrict__ bq)
{
    __shared__ float4 sW[8][32];   // x-part of rows 0..7
    const int tid = threadIdx.x, wid = tid >> 5, lane = tid & 31;
    const float4* Wq4 = (const float4*)Wq;
    for (int i = tid; i < 256; i += 128) sW[i >> 5][i & 31] = Wq4[(i >> 5) * 64 + (i & 31)];
    __syncthreads();

    int base = blockIdx.x * 16 + wid * 4;
    #pragma unroll
    for (int k = 0; k < 4; k++) {
        int tb = base + k;
        float4 xv = ((const float4*)(inputs + (size_t)tb * INPUT_DIM))[lane];
        float acc[8];
        #pragma unroll
        for (int r = 0; r < 8; r++) {
            float4 w = sW[r][lane];
            float a = xv.x * w.x;
            a = fmaf(xv.y, w.y, a); a = fmaf(xv.z, w.z, a); a = fmaf(xv.w, w.w, a);
            acc[r] = a;
        }
        const unsigned FM = 0xffffffffu;
        int t0 = lane & 1;
        float s0 = t0 ? acc[0] : acc[1], s1 = t0 ? acc[2] : acc[3];
        float s2 = t0 ? acc[4] : acc[5], s3 = t0 ? acc[6] : acc[7];
        float r0 = __shfl_xor_sync(FM, s0, 1);
        float r1 = __shfl_xor_sync(FM, s1, 1);
        float r2 = __shfl_xor_sync(FM, s2, 1);
        float r3 = __shfl_xor_sync(FM, s3, 1);
        float w0_ = (t0 ? acc[1] : acc[0]) + r0;
        float w1_ = (t0 ? acc[3] : acc[2]) + r1;
        float w2_ = (t0 ? acc[5] : acc[4]) + r2;
        float w3_ = (t0 ? acc[7] : acc[6]) + r3;
        int t1 = (lane >> 1) & 1;
        float s4 = t1 ? w0_ : w1_, s5 = t1 ? w2_ : w3_;
        float r4 = __shfl_xor_sync(FM, s4, 2);
        float r5 = __shfl_xor_sync(FM, s5, 2);
        float x0_ = (t1 ? w1_ : w0_) + r4;
        float x1_ = (t1 ? w3_ : w2_) + r5;
        int t2 = (lane >> 2) & 1;
        float s6 = t2 ? x0_ : x1_;
        float r6 = __shfl_xor_sync(FM, s6, 4);
        float y = (t2 ? x1_ : x0_) + r6;
        y += __shfl_xor_sync(FM, y, 8);
        y += __shfl_xor_sync(FM, y, 16);
        if (lane < 8) g_qx[tb * NQ + lane] = y + bq[lane];
    }
}

// ---------------- recurrent kernel: one warp per batch element ----------------
__global__ __launch_bounds__(32)
void qlstm_all(const float* __restrict__ Wq,
               const float* __restrict__ pf,
               const float* __restrict__ pi_,
               const float* __restrict__ pg,
               const float* __restrict__ po,
               const float* __restrict__ Wf, const float* __restrict__ bf,
               const float* __restrict__ Wi, const float* __restrict__ bi,
               const float* __restrict__ Wg, const float* __restrict__ bg,
               const float* __restrict__ Wo, const float* __restrict__ bo,
               float* __restrict__ out)
{
    const int b    = blockIdx.x;
    const int lane = threadIdx.x;
    const int g    = lane >> 3;      // gate 0..3 (f,i,g,o)
    const int v    = lane & 7;       // output wire for the DP
    const unsigned FM = 0xffffffffu;

    __shared__ float4 sWg[NQ][4][32];            // 16KB: (Wf,Wi,Wg,Wo) at h=4*lane+u
    __shared__ __align__(16) float zsm[2][NQ][4];// double-buffered [wire][gate]

    // ---- per-lane circuit constants (lane's gate), FULL angles ----
    float Cg[NQ], Sg[NQ], cg[NQ], sg[NQ];
    {
        const float* prm = (g == 0) ? pf : (g == 1) ? pi_ : (g == 2) ? pg : po;
        #pragma unroll
        for (int w = 0; w < NQ; w++) {
            __sincosf(prm[w],      &Sg[w], &Cg[w]);   // d0 layer
            __sincosf(prm[NQ + w], &sg[w], &cg[w]);   // d1 layer
        }
    }
    // ---- Wq h-part in REGISTERS: rW[r] = Wq[r][128 + 4*lane .. +3] ----
    float4 rW[8];
    {
        const float4* Wq4 = (const float4*)Wq;
        #pragma unroll
        for (int r = 0; r < 8; r++) rW[r] = Wq4[r * 64 + 32 + lane];
    }
    // ---- epilogue weights to smem ----
    for (int i = lane; i < HIDDEN * NQ; i += 32) {
        int h = i >> 3, w = i & 7;
        sWg[w][h & 3][h >> 2] = make_float4(Wf[i], Wi[i], Wg[i], Wo[i]);
    }
    // per-lane LSTM constants for units 4*lane..4*lane+3
    const float4 bf4 = ((const float4*)bf)[lane];
    const float4 bi4 = ((const float4*)bi)[lane];
    const float4 bg4 = ((const float4*)bg)[lane];
    const float4 bo4 = ((const float4*)bo)[lane];

    float4 hv = make_float4(0.f, 0.f, 0.f, 0.f);   // h[4l..4l+3], registers only
    float  cv[4] = {0.f, 0.f, 0.f, 0.f};

    float qxc = g_qx[(size_t)b * NQ + v];    // t=0, row v
    __syncwarp();                            // sWg visible

    for (int t = 0; t < SEQ; t++) {
        const int buf = t & 1;

        // ---- h-part GEMM from registers, tree-depth partials ----
        float acc[8];
        #pragma unroll
        for (int r = 0; r < 8; r++) {
            float4 w = rW[r];
            float a01 = fmaf(hv.y, w.y, hv.x * w.x);
            float a23 = fmaf(hv.w, w.w, hv.z * w.z);
            acc[r] = a01 + a23;
        }
        float y;
        {
            int t0 = lane & 1;
            float s0 = t0 ? acc[0] : acc[1], s1 = t0 ? acc[2] : acc[3];
            float s2 = t0 ? acc[4] : acc[5], s3 = t0 ? acc[6] : acc[7];
            float r0 = __shfl_xor_sync(FM, s0, 1);
            float r1 = __shfl_xor_sync(FM, s1, 1);
            float r2 = __shfl_xor_sync(FM, s2, 1);
            float r3 = __shfl_xor_sync(FM, s3, 1);
            float w0_ = (t0 ? acc[1] : acc[0]) + r0;
            float w1_ = (t0 ? acc[3] : acc[2]) + r1;
            float w2_ = (t0 ? acc[5] : acc[4]) + r2;
            float w3_ = (t0 ? acc[7] : acc[6]) + r3;
            int t1 = (lane >> 1) & 1;
            float s4 = t1 ? w0_ : w1_, s5 = t1 ? w2_ : w3_;
            float r4 = __shfl_xor_sync(FM, s4, 2);
            float r5 = __shfl_xor_sync(FM, s5, 2);
            float x0_ = (t1 ? w1_ : w0_) + r4;
            float x1_ = (t1 ? w3_ : w2_) + r5;
            int t2 = (lane >> 2) & 1;
            float s6 = t2 ? x0_ : x1_;
            float r6 = __shfl_xor_sync(FM, s6, 4);
            y = (t2 ? x1_ : x0_) + r6;
            y += __shfl_xor_sync(FM, y, 8);
            y += __shfl_xor_sync(FM, y, 16);   // row (lane&7) total, ALL lanes
        }
        // prefetch next qx (h-independent, off critical path)
        float qxn = 0.f;
        if (t + 1 < SEQ) qxn = g_qx[((size_t)(t + 1) * BATCH + b) * NQ + v];

        // sincos of this lane's row (wire v); cs of wire j lives in lanes with v=j
        float sq, cq;
        __sincosf(y + qxc, &sq, &cq);

        // ---- Heisenberg DP (real 4-state), lane computes z[g][v] ----
        float a_ = 1.f, bb = 0.f, c_ = 0.f, d_ = 0.f;
        #pragma unroll
        for (int j = 7; j >= 0; j--) {
            float zf, xf, yf;
            if (j == 7) { zf = 0.f; xf = 1.f; yf = 0.f; }
            else {
                float cqj = __shfl_sync(FM, cq, j + 1);
                float sqj = __shfl_sync(FM, sq, j + 1);
                zf = Cg[j + 1] * cqj;
                xf = Sg[j + 1] * cqj;
                yf = -sqj;
            }
            if (j <= v) {
                float cj = cg[j], sj = sg[j];
                float na = cj * fmaf(yf, d_, bb * zf);
                float nb = cj * fmaf(xf, c_, a_);
                float nc = -sj * fmaf(xf, a_, c_);
                float nd = -sj * fmaf(-yf, bb, d_ * zf);
                a_ = na; bb = nb; c_ = nc; d_ = nd;
            }
        }
        {
            float cq0 = __shfl_sync(FM, cq, 0);
            float sq0 = __shfl_sync(FM, sq, 0);
            float E = a_;
            E = fmaf(Sg[0] * cq0, c_, E);
            E = fmaf(Cg[0] * cq0, bb, E);
            E = fmaf(-sq0, d_, E);
            zsm[buf][v][g] = E;
        }
        __syncwarp();   // STS -> LDS cross-lane handoff (only sync in loop)

        // ---- epilogue: units 4*lane+u; z broadcast from smem ----
        float4 zw[8];
        #pragma unroll
        for (int w = 0; w < NQ; w++) zw[w] = *(const float4*)&zsm[buf][w][0];
        u64 zfi[8], zgo[8];
        #pragma unroll
        for (int w = 0; w < NQ; w++) {
            zfi[w] = pk(zw[w].x, zw[w].y);
            zgo[w] = pk(zw[w].z, zw[w].w);
        }

        float hn[4];
        #pragma unroll
        for (int u = 0; u < 4; u++) {
            float bfv = (u == 0) ? bf4.x : (u == 1) ? bf4.y : (u == 2) ? bf4.z : bf4.w;
            float biv = (u == 0) ? bi4.x : (u == 1) ? bi4.y : (u == 2) ? bi4.z : bi4.w;
            float bgv = (u == 0) ? bg4.x : (u == 1) ? bg4.y : (u == 2) ? bg4.z : bg4.w;
            float bov = (u == 0) ? bo4.x : (u == 1) ? bo4.y : (u == 2) ? bo4.z : bo4.w;
            // split even/odd wire chains to halve accumulation depth
            u64 aA = pk(bfv, biv), aB = pk(0.f, 0.f);
            u64 bA = pk(bgv, bov), bB = pk(0.f, 0.f);
            #pragma unroll
            for (int w = 0; w < NQ; w += 2) {
                float4 w0 = sWg[w][u][lane];
                float4 w1 = sWg[w + 1][u][lane];
                FMA2(aA, zfi[w],     pk(w0.x, w0.y), aA);
                FMA2(aB, zfi[w + 1], pk(w1.x, w1.y), aB);
                FMA2(bA, zgo[w],     pk(w0.z, w0.w), bA);
                FMA2(bB, zgo[w + 1], pk(w1.z, w1.w), bB);
            }
            u64 accfi, accgo;
            ADD2(accfi, aA, aB);
            ADD2(accgo, bA, bB);
            float accf, acci, accg, acco;
            upk(accfi, accf, acci);
            upk(accgo, accg, acco);

            float fg = __fdividef(1.f, 1.f + __expf(-accf));
            float ig = __fdividef(1.f, 1.f + __expf(-acci));
            float e2 = __expf(2.f * accg);
            float gg = __fdividef(e2 - 1.f, e2 + 1.f);
            float og = __fdividef(1.f, 1.f + __expf(-acco));

            cv[u] = fmaf(fg, cv[u], ig * gg);
            float e2c = __expf(2.f * cv[u]);
            hn[u] = og * __fdividef(e2c - 1.f, e2c + 1.f);
        }
        hv = make_float4(hn[0], hn[1], hn[2], hn[3]);   // h stays in registers

        ((float4*)(out + (size_t)t * BATCH * HIDDEN + (size_t)b * HIDDEN))[lane] = hv;
        qxc = qxn;
        // no tail sync: zsm is double-buffered
    }

    // ---- final hx, cx ----
    size_t base = (size_t)SEQ * BATCH * HIDDEN;
    ((float4*)(out + base + (size_t)b * HIDDEN))[lane] = hv;
    ((float4*)(out + base + (size_t)BATCH * HIDDEN + (size_t)b * HIDDEN))[lane]
        = make_float4(cv[0], cv[1], cv[2], cv[3]);
}

extern "C" void kernel_launch(void* const* d_in, const int* in_sizes, int n_in,
                              void* d_out, int out_size)
{
    const float* inputs = (const float*)d_in[0];
    const float* Wq     = (const float*)d_in[1];
    const float* bq     = (const float*)d_in[2];
    const float* pf     = (const float*)d_in[3];
    const float* pi_    = (const float*)d_in[4];
    const float* pg     = (const float*)d_in[5];
    const float* po     = (const float*)d_in[6];
    const float* Wf     = (const float*)d_in[7];
    const float* bf     = (const float*)d_in[8];
    const float* Wi     = (const float*)d_in[9];
    const float* bi     = (const float*)d_in[10];
    const float* Wg     = (const float*)d_in[11];
    const float* bg     = (const float*)d_in[12];
    const float* Wo     = (const float*)d_in[13];
    const float* bo     = (const float*)d_in[14];
    float* out = (float*)d_out;

    qx_pre<<<4096, 128>>>(inputs, Wq, bq);
    qlstm_all<<<BATCH, 32>>>(Wq, pf, pi_, pg, po,
                             Wf, bf, Wi, bi, Wg, bg, Wo, bo, out);
}